// round 8
// baseline (speedup 1.0000x reference)
#include <cuda_runtime.h>
#include <cuda_bf16.h>
#include <cstdint>

// Problem constants (match reference)
#define N_NODES     100000
#define INPUT_DIM   10000
#define OUTPUT_DIM  128
#define NNZ_TOTAL   2000000
#define INV_KEEP    ((float)(1.0/0.9))

// Launch geometry
#define THREADS_PER_BLOCK 256
#define WARPS_PER_BLOCK   (THREADS_PER_BLOCK / 32)
#define NUM_BLOCKS        1184                       // 8 blocks/SM * 148 SMs
#define TOTAL_WARPS       (NUM_BLOCKS * WARPS_PER_BLOCK)   // 9472
#define CHUNK             ((NNZ_TOTAL + TOTAL_WARPS - 1) / TOTAL_WARPS)  // 212

// keep_mask dtype mode: 0 = uint8/bool, 1 = int32, 2 = float32
__device__ int g_mask_mode;

// ---------------------------------------------------------------------------
// Detect the on-device dtype of keep_mask by byte-pattern inspection.
//   int32 0/1 little-endian: nonzero bytes only at offset%4==0
//   float32 0.0/1.0:        nonzero bytes only at offset%4 in {2,3} (00 00 80 3F)
//   uint8 0/1:              nonzero bytes at all offsets (~90% ones)
// Deterministic: same input bytes -> same mode on every call.
// ---------------------------------------------------------------------------
__global__ void detect_mask_kernel(const unsigned char* __restrict__ m) {
    if (threadIdx.x != 0 || blockIdx.x != 0) return;
    int nz0 = 0, nz_rest = 0;
    #pragma unroll 4
    for (int i = 0; i < 1024; ++i) {
        if (m[i * 4 + 0]) nz0++;
        if (m[i * 4 + 1] | m[i * 4 + 2] | m[i * 4 + 3]) nz_rest++;
    }
    int mode;
    if (nz_rest == 0)      mode = 1;   // int32
    else if (nz0 == 0)     mode = 2;   // float32
    else                   mode = 0;   // uint8 / bool
    g_mask_mode = mode;
}

// ---------------------------------------------------------------------------
// out[r][c] = bias[c] for all rows (out is poisoned to 0xAA by the harness;
// zero-nnz rows must still carry the bias, and boundary-row atomics add onto
// this baseline).
// ---------------------------------------------------------------------------
__global__ void init_out_kernel(float* __restrict__ out,
                                const float* __restrict__ bias) {
    const int total4 = (N_NODES * OUTPUT_DIM) / 4;     // float4 elements
    float4* out4 = reinterpret_cast<float4*>(out);
    const float4* bias4 = reinterpret_cast<const float4*>(bias);
    for (int j = blockIdx.x * blockDim.x + threadIdx.x; j < total4;
         j += gridDim.x * blockDim.x) {
        out4[j] = bias4[j & 31];                        // 32 float4 per row
    }
}

// ---------------------------------------------------------------------------
// Main SpMM. One warp per contiguous nnz chunk of CHUNK entries. Lane l owns
// output columns [4l, 4l+4) and accumulates a float4. Rows are sorted, so
// same-row nnz are contiguous:
//   - a row flushed on an INTERIOR row-change is wholly owned by this warp
//     (prev warps hold rows <= first_row < cur_row; next warps hold rows
//      >= the row that triggered the change > cur_row)  -> plain float4 store
//      of bias + acc, overwriting the init value.
//   - the chunk's first row and last row may be shared with neighbor warps
//      -> atomicAdd(acc) onto the bias-initialized output.
// ---------------------------------------------------------------------------
__global__ void __launch_bounds__(THREADS_PER_BLOCK)
spmm_dropout_kernel(const float* __restrict__ values,
                    const int*   __restrict__ rows,
                    const int*   __restrict__ cols,
                    const unsigned char* __restrict__ mask_raw,
                    const float* __restrict__ weights,
                    const float* __restrict__ bias,
                    float*       __restrict__ out) {
    const int warp = (blockIdx.x * THREADS_PER_BLOCK + threadIdx.x) >> 5;
    const int lane = threadIdx.x & 31;

    int start = warp * CHUNK;
    if (start >= NNZ_TOTAL) return;
    int end = start + CHUNK;
    if (end > NNZ_TOTAL) end = NNZ_TOTAL;

    const int mode = g_mask_mode;
    const int c0 = lane * 4;

    const float4 b4 = *reinterpret_cast<const float4*>(bias + c0);

    const int*   mask_i32 = reinterpret_cast<const int*>(mask_raw);
    const float* mask_f32 = reinterpret_cast<const float*>(mask_raw);

    float4 acc = make_float4(0.f, 0.f, 0.f, 0.f);
    int cur_row = __ldg(rows + start);
    const int first_row = cur_row;
    int next_r = cur_row;                         // prefetched rows[i]

    for (int i = start; i < end; ++i) {
        const int r = next_r;
        // prefetch next row index one iteration ahead
        next_r = (i + 1 < end) ? __ldg(rows + i + 1) : r;

        if (r != cur_row) {
            float* dst = out + cur_row * OUTPUT_DIM + c0;
            if (cur_row == first_row) {
                // possibly shared with the previous warp's chunk
                atomicAdd(dst + 0, acc.x);
                atomicAdd(dst + 1, acc.y);
                atomicAdd(dst + 2, acc.z);
                atomicAdd(dst + 3, acc.w);
            } else {
                // exclusively owned: overwrite the bias-initialized value
                float4 o = make_float4(acc.x + b4.x, acc.y + b4.y,
                                       acc.z + b4.z, acc.w + b4.w);
                *reinterpret_cast<float4*>(dst) = o;
            }
            acc = make_float4(0.f, 0.f, 0.f, 0.f);
            cur_row = r;
        }

        float v = __ldg(values + i);
        bool keep;
        if (mode == 0)      keep = (mask_raw[i] != 0);
        else if (mode == 1) keep = (mask_i32[i] != 0);
        else                keep = (mask_f32[i] != 0.0f);
        v = keep ? v * INV_KEEP : 0.0f;

        const int c = __ldg(cols + i);
        const float4 w =
            *reinterpret_cast<const float4*>(weights + c * OUTPUT_DIM + c0);
        acc.x += v * w.x;
        acc.y += v * w.y;
        acc.z += v * w.z;
        acc.w += v * w.w;
    }

    // Final flush: the chunk's last row may extend into the next warp's
    // chunk -> atomic. (Also correct when cur_row == first_row.)
    {
        float* dst = out + cur_row * OUTPUT_DIM + c0;
        atomicAdd(dst + 0, acc.x);
        atomicAdd(dst + 1, acc.y);
        atomicAdd(dst + 2, acc.z);
        atomicAdd(dst + 3, acc.w);
    }
}

// ---------------------------------------------------------------------------
// Harness entry point. Input order per metadata:
//   0: values    (float32, NNZ)
//   1: rows      (int32,   NNZ, sorted ascending)
//   2: cols      (int32,   NNZ)
//   3: keep_mask (bool -> on-device dtype detected at runtime, NNZ)
//   4: weights   (float32, INPUT_DIM*OUTPUT_DIM)
//   5: bias      (float32, OUTPUT_DIM)
// Output: float32 [N_NODES, OUTPUT_DIM]
// ---------------------------------------------------------------------------
extern "C" void kernel_launch(void* const* d_in, const int* in_sizes, int n_in,
                              void* d_out, int out_size) {
    const float*         values  = (const float*)d_in[0];
    const int*           rows    = (const int*)d_in[1];
    const int*           cols    = (const int*)d_in[2];
    const unsigned char* mask    = (const unsigned char*)d_in[3];
    const float*         weights = (const float*)d_in[4];
    const float*         bias    = (const float*)d_in[5];
    float*               out     = (float*)d_out;

    detect_mask_kernel<<<1, 32>>>(mask);

    init_out_kernel<<<592, 256>>>(out, bias);

    spmm_dropout_kernel<<<NUM_BLOCKS, THREADS_PER_BLOCK>>>(
        values, rows, cols, mask, weights, bias, out);
}

// round 9
// speedup vs baseline: 2.3289x; 2.3289x over previous
#include <cuda_runtime.h>
#include <cuda_bf16.h>
#include <cstdint>

// Problem constants (match reference)
#define N_NODES     100000
#define INPUT_DIM   10000
#define OUTPUT_DIM  128
#define NNZ_TOTAL   2000000
#define INV_KEEP    ((float)(1.0/0.9))

// Launch geometry for the main spmm
#define THREADS_PER_BLOCK 256
#define WARPS_PER_BLOCK   (THREADS_PER_BLOCK / 32)
#define NUM_BLOCKS        1184                       // 8 blocks/SM * 148 SMs
#define TOTAL_WARPS       (NUM_BLOCKS * WARPS_PER_BLOCK)   // 9472
#define CHUNK             ((NNZ_TOTAL + TOTAL_WARPS - 1) / TOTAL_WARPS)  // 212

// keep_mask dtype mode: 0 = uint8/bool, 1 = int32, 2 = float32
__device__ int g_mask_mode;

// Packed per-nnz record: [63:32] = v bits (dropout applied),
//                        [31:14] = row (17 bits used), [13:0] = col (14 bits).
__device__ unsigned long long g_packed[NNZ_TOTAL];   // 16 MB static scratch

// ---------------------------------------------------------------------------
// Warp-parallel mask-dtype detection (coalesced loads + ballot reduce).
//   int32 0/1 LE:    nonzero bytes only at offset%4==0
//   float32 0.0/1.0: nonzero bytes only at offset%4 in {2,3} (00 00 80 3F)
//   uint8 0/1:       nonzero bytes at all offsets (~90% ones)
// ---------------------------------------------------------------------------
__global__ void detect_mask_kernel(const unsigned char* __restrict__ m) {
    const unsigned int lane = threadIdx.x;            // 32 threads
    const uint32_t* m32 = reinterpret_cast<const uint32_t*>(m);
    int nz0 = 0, nz_rest = 0;
    #pragma unroll
    for (int k = 0; k < 32; ++k) {                    // 32*32 = 1024 words = 4096 B
        uint32_t w = m32[k * 32 + lane];
        if (w & 0x000000FFu) nz0++;
        if (w & 0xFFFFFF00u) nz_rest++;
    }
    // warp reduce
    #pragma unroll
    for (int off = 16; off > 0; off >>= 1) {
        nz0     += __shfl_xor_sync(0xFFFFFFFFu, nz0,     off);
        nz_rest += __shfl_xor_sync(0xFFFFFFFFu, nz_rest, off);
    }
    if (lane == 0) {
        int mode;
        if (nz_rest == 0)      mode = 1;   // int32
        else if (nz0 == 0)     mode = 2;   // float32
        else                   mode = 0;   // uint8 / bool
        g_mask_mode = mode;
    }
}

// ---------------------------------------------------------------------------
// Pre-pack: fold dropout + mask decode; pack (v, row, col) into one uint64.
// Streams ~48 MB; removes 3 LDGs + the mask branch from the hot loop.
// ---------------------------------------------------------------------------
__global__ void __launch_bounds__(256)
prep_kernel(const float* __restrict__ values,
            const int*   __restrict__ rows,
            const int*   __restrict__ cols,
            const unsigned char* __restrict__ mask_raw) {
    const int mode = g_mask_mode;
    const int*   mask_i32 = reinterpret_cast<const int*>(mask_raw);
    const float* mask_f32 = reinterpret_cast<const float*>(mask_raw);
    for (int i = blockIdx.x * blockDim.x + threadIdx.x; i < NNZ_TOTAL;
         i += gridDim.x * blockDim.x) {
        float v = values[i];
        bool keep;
        if (mode == 0)      keep = (mask_raw[i] != 0);
        else if (mode == 1) keep = (mask_i32[i] != 0);
        else                keep = (mask_f32[i] != 0.0f);
        v = keep ? v * INV_KEEP : 0.0f;
        uint32_t lo = ((uint32_t)rows[i] << 14) | (uint32_t)cols[i];
        g_packed[i] = ((unsigned long long)__float_as_uint(v) << 32) | lo;
    }
}

// ---------------------------------------------------------------------------
// out[r][c] = bias[c] for all rows (out is poisoned to 0xAA by the harness;
// zero-nnz rows must carry the bias, and boundary-row atomics add onto it).
// ---------------------------------------------------------------------------
__global__ void init_out_kernel(float* __restrict__ out,
                                const float* __restrict__ bias) {
    const int total4 = (N_NODES * OUTPUT_DIM) / 4;     // float4 elements
    float4* out4 = reinterpret_cast<float4*>(out);
    const float4* bias4 = reinterpret_cast<const float4*>(bias);
    for (int j = blockIdx.x * blockDim.x + threadIdx.x; j < total4;
         j += gridDim.x * blockDim.x) {
        out4[j] = bias4[j & 31];                        // 32 float4 per row
    }
}

// ---------------------------------------------------------------------------
// Main SpMM. One warp per contiguous nnz chunk of CHUNK entries. Lane l owns
// output columns [4l, 4l+4) and accumulates a float4. Rows are sorted, so
// same-row nnz are contiguous:
//   - a row flushed on an INTERIOR row-change is wholly owned by this warp
//      -> plain float4 store of bias + acc (overwrites the init value).
//   - the chunk's first and last rows may be shared with neighbor warps
//      -> atomicAdd(acc) onto the bias-initialized output.
// Hot loop: 1 broadcast LDG.64 (packed) + 1 LDG.128 (W row slice).
// ---------------------------------------------------------------------------
__global__ void __launch_bounds__(THREADS_PER_BLOCK)
spmm_dropout_kernel(const float* __restrict__ weights,
                    const float* __restrict__ bias,
                    float*       __restrict__ out) {
    const int warp = (blockIdx.x * THREADS_PER_BLOCK + threadIdx.x) >> 5;
    const int lane = threadIdx.x & 31;

    int start = warp * CHUNK;
    if (start >= NNZ_TOTAL) return;
    int end = start + CHUNK;
    if (end > NNZ_TOTAL) end = NNZ_TOTAL;

    const int c0 = lane * 4;
    const float4 b4 = *reinterpret_cast<const float4*>(bias + c0);

    float4 acc = make_float4(0.f, 0.f, 0.f, 0.f);

    unsigned long long p = __ldg(&g_packed[start]);
    int cur_row = (int)(((uint32_t)p) >> 14);
    const int first_row = cur_row;

    for (int i = start; i < end; ++i) {
        const uint32_t lo = (uint32_t)p;
        const float v = __uint_as_float((uint32_t)(p >> 32));
        const int r = (int)(lo >> 14);
        const int c = (int)(lo & 0x3FFFu);

        // prefetch next packed record (hides its latency behind the W load)
        if (i + 1 < end) p = __ldg(&g_packed[i + 1]);

        if (r != cur_row) {
            float* dst = out + cur_row * OUTPUT_DIM + c0;
            if (cur_row == first_row) {
                atomicAdd(dst + 0, acc.x);
                atomicAdd(dst + 1, acc.y);
                atomicAdd(dst + 2, acc.z);
                atomicAdd(dst + 3, acc.w);
            } else {
                float4 o = make_float4(acc.x + b4.x, acc.y + b4.y,
                                       acc.z + b4.z, acc.w + b4.w);
                *reinterpret_cast<float4*>(dst) = o;
            }
            acc = make_float4(0.f, 0.f, 0.f, 0.f);
            cur_row = r;
        }

        const float4 w =
            *reinterpret_cast<const float4*>(weights + c * OUTPUT_DIM + c0);
        acc.x += v * w.x;
        acc.y += v * w.y;
        acc.z += v * w.z;
        acc.w += v * w.w;
    }

    // Final flush: the chunk's last row may extend into the next warp's chunk.
    {
        float* dst = out + cur_row * OUTPUT_DIM + c0;
        atomicAdd(dst + 0, acc.x);
        atomicAdd(dst + 1, acc.y);
        atomicAdd(dst + 2, acc.z);
        atomicAdd(dst + 3, acc.w);
    }
}

// ---------------------------------------------------------------------------
// Harness entry point. Input order per metadata:
//   0: values    (float32, NNZ)
//   1: rows      (int32,   NNZ, sorted ascending)
//   2: cols      (int32,   NNZ)
//   3: keep_mask (bool -> on-device dtype detected at runtime, NNZ)
//   4: weights   (float32, INPUT_DIM*OUTPUT_DIM)
//   5: bias      (float32, OUTPUT_DIM)
// Output: float32 [N_NODES, OUTPUT_DIM]
// ---------------------------------------------------------------------------
extern "C" void kernel_launch(void* const* d_in, const int* in_sizes, int n_in,
                              void* d_out, int out_size) {
    const float*         values  = (const float*)d_in[0];
    const int*           rows    = (const int*)d_in[1];
    const int*           cols    = (const int*)d_in[2];
    const unsigned char* mask    = (const unsigned char*)d_in[3];
    const float*         weights = (const float*)d_in[4];
    const float*         bias    = (const float*)d_in[5];
    float*               out     = (float*)d_out;

    detect_mask_kernel<<<1, 32>>>(mask);
    prep_kernel<<<1184, 256>>>(values, rows, cols, mask);
    init_out_kernel<<<592, 256>>>(out, bias);
    spmm_dropout_kernel<<<NUM_BLOCKS, THREADS_PER_BLOCK>>>(weights, bias, out);
}

// round 10
// speedup vs baseline: 2.5392x; 1.0903x over previous
#include <cuda_runtime.h>
#include <cuda_bf16.h>
#include <cstdint>

// Problem constants (match reference)
#define N_NODES     100000
#define INPUT_DIM   10000
#define OUTPUT_DIM  128
#define NNZ_TOTAL   2000000
#define INV_KEEP    ((float)(1.0/0.9))

// Launch geometry for the main spmm: 6 CTAs/SM * 148 SMs = one exact wave at
// the 42-reg occupancy point (unroll-2 needs ~40 regs).
#define THREADS_PER_BLOCK 256
#define WARPS_PER_BLOCK   (THREADS_PER_BLOCK / 32)
#define NUM_BLOCKS        888
#define TOTAL_WARPS       (NUM_BLOCKS * WARPS_PER_BLOCK)   // 7104
#define CHUNK             282   // ceil(2e6/7104) -> even, so every chunk start
                                // and size is even (pair loop needs no tail)

// keep_mask dtype mode: 0 = uint8/bool, 1 = int32, 2 = float32
__device__ int g_mask_mode;

// Packed per-nnz record: [63:32] = v bits (dropout applied),
//                        [31:14] = row (17 bits used), [13:0] = col (14 bits).
__device__ __align__(16) unsigned long long g_packed[NNZ_TOTAL];  // 16 MB scratch

// ---------------------------------------------------------------------------
// Warp-parallel mask-dtype detection (coalesced loads + shfl reduce).
//   int32 0/1 LE:    nonzero bytes only at offset%4==0
//   float32 0.0/1.0: nonzero bytes only at offset%4 in {2,3} (00 00 80 3F)
//   uint8 0/1:       nonzero bytes at all offsets (~90% ones)
// ---------------------------------------------------------------------------
__global__ void detect_mask_kernel(const unsigned char* __restrict__ m) {
    const unsigned int lane = threadIdx.x;            // 32 threads
    const uint32_t* m32 = reinterpret_cast<const uint32_t*>(m);
    int nz0 = 0, nz_rest = 0;
    #pragma unroll
    for (int k = 0; k < 32; ++k) {                    // 1024 words = 4096 B
        uint32_t w = m32[k * 32 + lane];
        if (w & 0x000000FFu) nz0++;
        if (w & 0xFFFFFF00u) nz_rest++;
    }
    #pragma unroll
    for (int off = 16; off > 0; off >>= 1) {
        nz0     += __shfl_xor_sync(0xFFFFFFFFu, nz0,     off);
        nz_rest += __shfl_xor_sync(0xFFFFFFFFu, nz_rest, off);
    }
    if (lane == 0) {
        int mode;
        if (nz_rest == 0)      mode = 1;   // int32
        else if (nz0 == 0)     mode = 2;   // float32
        else                   mode = 0;   // uint8 / bool
        g_mask_mode = mode;
    }
}

// ---------------------------------------------------------------------------
// Fused prep + init (both pure streaming, ~93 MB total):
//   phase 1: out[r][c] = bias[c] for all rows (out is poisoned to 0xAA; rows
//            with zero nnz must carry bias; boundary atomics add onto it)
//   phase 2: fold dropout + mask decode, pack (v,row,col) into one uint64
// ---------------------------------------------------------------------------
__global__ void __launch_bounds__(256)
prep_init_kernel(const float* __restrict__ values,
                 const int*   __restrict__ rows,
                 const int*   __restrict__ cols,
                 const unsigned char* __restrict__ mask_raw,
                 const float* __restrict__ bias,
                 float*       __restrict__ out) {
    const int tid    = blockIdx.x * blockDim.x + threadIdx.x;
    const int stride = gridDim.x * blockDim.x;

    // phase 1: bias broadcast
    {
        const int total4 = (N_NODES * OUTPUT_DIM) / 4;     // float4 elements
        float4* out4 = reinterpret_cast<float4*>(out);
        const float4* bias4 = reinterpret_cast<const float4*>(bias);
        for (int j = tid; j < total4; j += stride)
            out4[j] = bias4[j & 31];                        // 32 float4 per row
    }

    // phase 2: pack
    const int mode = g_mask_mode;
    const int*   mask_i32 = reinterpret_cast<const int*>(mask_raw);
    const float* mask_f32 = reinterpret_cast<const float*>(mask_raw);
    for (int i = tid; i < NNZ_TOTAL; i += stride) {
        float v = values[i];
        bool keep;
        if (mode == 0)      keep = (mask_raw[i] != 0);
        else if (mode == 1) keep = (mask_i32[i] != 0);
        else                keep = (mask_f32[i] != 0.0f);
        v = keep ? v * INV_KEEP : 0.0f;
        uint32_t lo = ((uint32_t)rows[i] << 14) | (uint32_t)cols[i];
        g_packed[i] = ((unsigned long long)__float_as_uint(v) << 32) | lo;
    }
}

// ---------------------------------------------------------------------------
// Main SpMM, unroll-2. One warp per contiguous even-sized nnz chunk. Lane l
// owns output columns [4l, 4l+4). Rows sorted => same-row nnz contiguous:
//   - rows flushed on an INTERIOR row-change are exclusively owned by this
//     warp -> plain float4 store of bias + acc (overwrites the init value).
//   - the chunk's first and last rows may be shared with neighbor warps
//     -> atomicAdd(acc) onto the bias-initialized output.
// Per pair of nnz: one broadcast LDG.128 (2 packed records) + two W LDG.128s
// issued back-to-back BEFORE the row-change branches (MLP=2 on the gather).
// ---------------------------------------------------------------------------
__global__ void __launch_bounds__(THREADS_PER_BLOCK, 6)
spmm_dropout_kernel(const float* __restrict__ weights,
                    const float* __restrict__ bias,
                    float*       __restrict__ out) {
    const int warp = (blockIdx.x * THREADS_PER_BLOCK + threadIdx.x) >> 5;
    const int lane = threadIdx.x & 31;

    int start = warp * CHUNK;                 // even
    if (start >= NNZ_TOTAL) return;
    int end = start + CHUNK;
    if (end > NNZ_TOTAL) end = NNZ_TOTAL;     // still even (NNZ even)

    const int c0 = lane * 4;
    const float4 b4 = *reinterpret_cast<const float4*>(bias + c0);

    const ulonglong2* packed2 = reinterpret_cast<const ulonglong2*>(g_packed);

    float4 acc = make_float4(0.f, 0.f, 0.f, 0.f);

    ulonglong2 pp = __ldg(&packed2[start >> 1]);
    int cur_row = (int)((uint32_t)pp.x >> 14);
    const int first_row = cur_row;

    for (int i = start; i < end; i += 2) {
        const unsigned long long p0 = pp.x, p1 = pp.y;
        const uint32_t lo0 = (uint32_t)p0, lo1 = (uint32_t)p1;
        const float v0 = __uint_as_float((uint32_t)(p0 >> 32));
        const float v1 = __uint_as_float((uint32_t)(p1 >> 32));
        const int cA = (int)(lo0 & 0x3FFFu), rA = (int)(lo0 >> 14);
        const int cB = (int)(lo1 & 0x3FFFu), rB = (int)(lo1 >> 14);

        // Issue both W gathers before any branch -> 2 loads in flight.
        const float4 w0 =
            *reinterpret_cast<const float4*>(weights + cA * OUTPUT_DIM + c0);
        const float4 w1 =
            *reinterpret_cast<const float4*>(weights + cB * OUTPUT_DIM + c0);

        // Prefetch the next packed pair.
        if (i + 2 < end) pp = __ldg(&packed2[(i + 2) >> 1]);

        if (rA != cur_row) {
            float* dst = out + cur_row * OUTPUT_DIM + c0;
            if (cur_row == first_row) {
                atomicAdd(dst + 0, acc.x); atomicAdd(dst + 1, acc.y);
                atomicAdd(dst + 2, acc.z); atomicAdd(dst + 3, acc.w);
            } else {
                *reinterpret_cast<float4*>(dst) =
                    make_float4(acc.x + b4.x, acc.y + b4.y,
                                acc.z + b4.z, acc.w + b4.w);
            }
            acc = make_float4(0.f, 0.f, 0.f, 0.f);
            cur_row = rA;
        }
        acc.x += v0 * w0.x; acc.y += v0 * w0.y;
        acc.z += v0 * w0.z; acc.w += v0 * w0.w;

        if (rB != cur_row) {
            float* dst = out + cur_row * OUTPUT_DIM + c0;
            if (cur_row == first_row) {
                atomicAdd(dst + 0, acc.x); atomicAdd(dst + 1, acc.y);
                atomicAdd(dst + 2, acc.z); atomicAdd(dst + 3, acc.w);
            } else {
                *reinterpret_cast<float4*>(dst) =
                    make_float4(acc.x + b4.x, acc.y + b4.y,
                                acc.z + b4.z, acc.w + b4.w);
            }
            acc = make_float4(0.f, 0.f, 0.f, 0.f);
            cur_row = rB;
        }
        acc.x += v1 * w1.x; acc.y += v1 * w1.y;
        acc.z += v1 * w1.z; acc.w += v1 * w1.w;
    }

    // Final flush: the chunk's last row may extend into the next warp's chunk.
    {
        float* dst = out + cur_row * OUTPUT_DIM + c0;
        atomicAdd(dst + 0, acc.x); atomicAdd(dst + 1, acc.y);
        atomicAdd(dst + 2, acc.z); atomicAdd(dst + 3, acc.w);
    }
}

// ---------------------------------------------------------------------------
// Harness entry point. Input order per metadata:
//   0: values    (float32, NNZ)
//   1: rows      (int32,   NNZ, sorted ascending)
//   2: cols      (int32,   NNZ)
//   3: keep_mask (bool -> on-device dtype detected at runtime, NNZ)
//   4: weights   (float32, INPUT_DIM*OUTPUT_DIM)
//   5: bias      (float32, OUTPUT_DIM)
// Output: float32 [N_NODES, OUTPUT_DIM]
// ---------------------------------------------------------------------------
extern "C" void kernel_launch(void* const* d_in, const int* in_sizes, int n_in,
                              void* d_out, int out_size) {
    const float*         values  = (const float*)d_in[0];
    const int*           rows    = (const int*)d_in[1];
    const int*           cols    = (const int*)d_in[2];
    const unsigned char* mask    = (const unsigned char*)d_in[3];
    const float*         weights = (const float*)d_in[4];
    const float*         bias    = (const float*)d_in[5];
    float*               out     = (float*)d_out;

    detect_mask_kernel<<<1, 32>>>(mask);
    prep_init_kernel<<<1184, 256>>>(values, rows, cols, mask, bias, out);
    spmm_dropout_kernel<<<NUM_BLOCKS, THREADS_PER_BLOCK>>>(weights, bias, out);
}